// round 15
// baseline (speedup 1.0000x reference)
#include <cuda_runtime.h>
#include <cuda_bf16.h>
#include <cstdint>

// ---------------- problem constants ----------------
#define Bc 16
#define Dc 64
#define Tc 8192
#define Kc 512
#define DT (Dc * Tc)        // 524288
#define BT (Bc * Tc)        // 131072
#define THREADS 512
#define GRID 148
#define NTILES (BT / 128)   // 1024 token tiles
#define CHUNK_B 16384       // 128 codewords x 64 K bf16 (ch only)
#define WIN 1e-3f           // >= 2*(mma err max ~2.4e-4) + grain 2.2e-5 + pack 2e-6, 2x margin

// ---------------- smem layout ----------------
#define SM_CN   0                            // 512 f32 norms
#define SM_CAND 2048                         // uint4 cand[128][2]
#define SM_KST  6144                         // int kst[128]
#define SM_A    6656                         // 128 tok x 128 k bf16 [xh|xl], 16x16 tiles
#define SM_B    (SM_A + 32768)               // 39424: ALL 4 chunks static, 64KB
#define SMEM_TOTAL (SM_B + 4 * CHUNK_B)      // 104960 B (~102.5 KB)

__device__ __align__(16) unsigned char g_B[4 * CHUNK_B];
__device__ float g_cn[Kc];

// ---------------- helpers ----------------
__device__ __forceinline__ uint32_t smem_u32(const void* p) {
    uint32_t a;
    asm("{ .reg .u64 t; cvta.to.shared.u64 t, %1; cvt.u32.u64 %0, t; }"
        : "=r"(a) : "l"(p));
    return a;
}

#define LDSM4(r0, r1, r2, r3, addr)                                          \
    asm volatile("ldmatrix.sync.aligned.m8n8.x4.shared.b16 {%0,%1,%2,%3}, [%4];" \
        : "=r"(r0), "=r"(r1), "=r"(r2), "=r"(r3) : "r"(addr))

#define MMA_BF16(c, a0, a1, a2, a3, b0, b1)                                  \
    asm volatile("mma.sync.aligned.m16n8k16.row.col.f32.bf16.bf16.f32 "      \
        "{%0,%1,%2,%3}, {%4,%5,%6,%7}, {%8,%9}, {%0,%1,%2,%3};"              \
        : "+f"((c)[0]), "+f"((c)[1]), "+f"((c)[2]), "+f"((c)[3])             \
        : "r"(a0), "r"(a1), "r"(a2), "r"(a3), "r"(b0), "r"(b1))

// packed score|idx: monotone-flipped float in high 23 bits, k in low 9 bits.
__device__ __forceinline__ uint32_t packsk(float s, int k) {
    uint32_t u = __float_as_uint(s);
    u = (u & 0x80000000u) ? ~u : (u | 0x80000000u);
    return (u & 0xFFFFFE00u) | (uint32_t)k;
}
__device__ __forceinline__ float unpk(uint32_t m) {
    m &= 0xFFFFFE00u;
    uint32_t u = (m & 0x80000000u) ? (m & 0x7FFFFFFFu) : ~m;
    return __uint_as_float(u);
}

#define INS4A(q, vv) do { uint32_t _v = (vv);                                \
    if (_v < (q)[3]) {                                                       \
        if (_v < (q)[0])      { (q)[3]=(q)[2]; (q)[2]=(q)[1]; (q)[1]=(q)[0]; (q)[0]=_v; } \
        else if (_v < (q)[1]) { (q)[3]=(q)[2]; (q)[2]=(q)[1]; (q)[1]=_v; }   \
        else if (_v < (q)[2]) { (q)[3]=(q)[2]; (q)[2]=_v; }                  \
        else                  { (q)[3]=_v; } } } while (0)
#define MRG4A(q, st) do {                                                    \
    uint32_t _a=__shfl_xor_sync(0xffffffffu, (q)[0], st);                    \
    uint32_t _b=__shfl_xor_sync(0xffffffffu, (q)[1], st);                    \
    uint32_t _c=__shfl_xor_sync(0xffffffffu, (q)[2], st);                    \
    uint32_t _d=__shfl_xor_sync(0xffffffffu, (q)[3], st);                    \
    INS4A(q,_a); INS4A(q,_b); INS4A(q,_c); INS4A(q,_d); } while (0)

__device__ __forceinline__ uint32_t pack_bf16(__nv_bfloat16 a, __nv_bfloat16 b) {
    uint16_t ua = *(uint16_t*)&a, ub = *(uint16_t*)&b;
    return (uint32_t)ua | ((uint32_t)ub << 16);
}

// ---------------- prep: bake B (ch only) + cn ----------------
// chunk c: tile (kt 0..3, n8 0..15) at (kt*16+n8)*256; in-tile: nrow*32 + kcol*2
__global__ void vq_prep(const float* __restrict__ cb)
{
    int r = blockIdx.x * blockDim.x + threadIdx.x;
    if (r >= Kc) return;
    const float* row = cb + r * Dc;
    unsigned char* base = g_B + (size_t)(r >> 7) * CHUNK_B;
    const int n8 = (r & 127) >> 3, nr = r & 7;
    float cn = 0.f;
    for (int d = 0; d < Dc; d++) {
        float v = row[d];
        cn = __fadd_rn(cn, __fmul_rn(v, v));     // serial ascending (matches ref)
        uint32_t off = (uint32_t)(((d >> 4) * 16 + n8) * 256 + nr * 32 + (d & 15) * 2);
        *(__nv_bfloat16*)(base + off) = __float2bfloat16_rn(v);
    }
    g_cn[r] = cn;
}

// ---------------- per-chunk compute: B loaded once, used by xh AND xl frags ----
__device__ __forceinline__ void do_chunk(uint32_t sB, int kq,
                                         const uint32_t (&afr)[8][4],
                                         const float* scn,
                                         uint32_t (&qA)[4], uint32_t (&qB)[4])
{
    float acc[8][4];
    #pragma unroll
    for (int a = 0; a < 8; a++)
        #pragma unroll
        for (int j = 0; j < 4; j++) acc[a][j] = 0.f;

    #pragma unroll
    for (int ktb = 0; ktb < 4; ktb++) {
        #pragma unroll
        for (int pr = 0; pr < 4; pr++) {
            uint32_t r0, r1, r2, r3;
            LDSM4(r0, r1, r2, r3, sB + (uint32_t)(ktb * 16 + pr * 2) * 256);
            // (xh + xl) . ch : both A frags accumulate into the same acc
            MMA_BF16(acc[2 * pr],     afr[ktb][0], afr[ktb][1], afr[ktb][2], afr[ktb][3], r0, r1);
            MMA_BF16(acc[2 * pr + 1], afr[ktb][0], afr[ktb][1], afr[ktb][2], afr[ktb][3], r2, r3);
            MMA_BF16(acc[2 * pr],     afr[ktb + 4][0], afr[ktb + 4][1], afr[ktb + 4][2], afr[ktb + 4][3], r0, r1);
            MMA_BF16(acc[2 * pr + 1], afr[ktb + 4][0], afr[ktb + 4][1], afr[ktb + 4][2], afr[ktb + 4][3], r2, r3);
        }
    }
    #pragma unroll
    for (int a = 0; a < 8; a++) {
        const int k = kq + a * 8;
        const float2 cn2 = *(const float2*)(scn + k);
        INS4A(qA, packsk(fmaf(-2.f, acc[a][0], cn2.x), k));
        INS4A(qA, packsk(fmaf(-2.f, acc[a][1], cn2.y), k + 1));
        INS4A(qB, packsk(fmaf(-2.f, acc[a][2], cn2.x), k));
        INS4A(qB, packsk(fmaf(-2.f, acc[a][3], cn2.y), k + 1));
    }
}

// ---------------- main ----------------
__global__ __launch_bounds__(THREADS, 1)
void vq_main(const float* __restrict__ x,
             const float* __restrict__ cb,
             float* __restrict__ out,
             int write_second)
{
    extern __shared__ char smem[];
    const uint32_t sb = smem_u32(smem);
    const int tid = threadIdx.x, wid = tid >> 5, lane = tid & 31;
    const int mt = wid >> 1, nh = wid & 1;     // M-tile 0..7, N-half 0..1
    float* scn = (float*)(smem + SM_CN);
    uint4* cand = (uint4*)(smem + SM_CAND);
    int* skst = (int*)(smem + SM_KST);

    for (int i = tid; i < Kc; i += THREADS) scn[i] = g_cn[i];

    // entire baked codebook (64KB) -> smem ONCE
    #pragma unroll
    for (int i = 0; i < 8; i++) {
        uint32_t s = sb + SM_B + (uint32_t)(tid + i * THREADS) * 16;
        const unsigned char* g = g_B + (size_t)(tid + i * THREADS) * 16;
        asm volatile("cp.async.cg.shared.global [%0], [%1], 16;" :: "r"(s), "l"(g));
    }
    asm volatile("cp.async.commit_group;" ::: "memory");

    const uint32_t aOff = (uint32_t)(lane & 15) * 32 + (uint32_t)(lane >> 4) * 16;
    const uint32_t bOff = (uint32_t)(lane & 7) * 32 + (uint32_t)((lane >> 3) & 1) * 16
                        + (uint32_t)(lane >> 4) * 256 + (uint32_t)nh * 2048;
    const uint32_t sA = sb + SM_A;

    for (int tile = blockIdx.x; tile < NTILES; tile += GRID) {
        const int b = tile >> 6, t0 = (tile & 63) * 128;
        const float* xbase = x + (size_t)b * DT + t0;

        // ---- A build: [xh | xl] 128x128, STS.128 (2 iters/thread) ----
        #pragma unroll
        for (int j = 0; j < 2; j++) {
            const int i = tid + j * THREADS;
            const int tl = i & 127, o = i >> 7;        // d-octet 0..7
            float v[8];
            #pragma unroll
            for (int e = 0; e < 8; e++) v[e] = xbase[(size_t)(o * 8 + e) * Tc + tl];
            uint4 hp, lp;
            {
                uint32_t h[4], l[4];
                #pragma unroll
                for (int p = 0; p < 4; p++) {
                    __nv_bfloat16 h0 = __float2bfloat16_rn(v[2 * p]);
                    __nv_bfloat16 h1 = __float2bfloat16_rn(v[2 * p + 1]);
                    __nv_bfloat16 l0 = __float2bfloat16_rn(v[2 * p]     - __bfloat162float(h0));
                    __nv_bfloat16 l1 = __float2bfloat16_rn(v[2 * p + 1] - __bfloat162float(h1));
                    h[p] = pack_bf16(h0, h1);
                    l[p] = pack_bf16(l0, l1);
                }
                hp = make_uint4(h[0], h[1], h[2], h[3]);
                lp = make_uint4(l[0], l[1], l[2], l[3]);
            }
            const uint32_t base = (uint32_t)((tl >> 4) * 8 + (o >> 1)) * 512
                                + (uint32_t)(tl & 15) * 32 + (uint32_t)(o & 1) * 16;
            *(uint4*)(smem + SM_A + base)            = hp;   // xh at kt = o>>1
            *(uint4*)(smem + SM_A + base + 4 * 512)  = lp;   // xl at kt = 4 + (o>>1)
        }
        asm volatile("cp.async.wait_group 0;" ::: "memory");   // first tile: B arrival
        __syncthreads();

        // ---- A fragments once per tile ----
        uint32_t afr[8][4];
        #pragma unroll
        for (int kt = 0; kt < 8; kt++)
            LDSM4(afr[kt][0], afr[kt][1], afr[kt][2], afr[kt][3],
                  sA + (uint32_t)(mt * 8 + kt) * 512 + aOff);

        uint32_t qA[4] = {0xFFFFFFFFu, 0xFFFFFFFFu, 0xFFFFFFFFu, 0xFFFFFFFFu};
        uint32_t qB[4] = {0xFFFFFFFFu, 0xFFFFFFFFu, 0xFFFFFFFFu, 0xFFFFFFFFu};
        const int kqL = nh * 64 + 2 * (lane & 3);

        // ---- 4 chunks, ALL static in smem: no barriers, warps skew freely ----
        #pragma unroll 1
        for (int c = 0; c < 4; c++)
            do_chunk(sb + SM_B + (uint32_t)c * CHUNK_B + bOff,
                     c * 128 + kqL, afr, scn, qA, qB);

        // ---- quad merge -> per-row-half top4 ----
        MRG4A(qA, 1); MRG4A(qA, 2);
        MRG4A(qB, 1); MRG4A(qB, 2);
        if ((lane & 3) == 0) {
            const int rA = mt * 16 + (lane >> 2);
            cand[rA * 2 + nh]       = make_uint4(qA[0], qA[1], qA[2], qA[3]);
            cand[(rA + 8) * 2 + nh] = make_uint4(qB[0], qB[1], qB[2], qB[3]);
        }
        __syncthreads();

        // ---- finalize (threads 0..127): window check + exact rescore ----
        int kstar = 0;
        bool heavy = false;
        if (tid < 128) {
            const uint4 u = cand[tid * 2], v = cand[tid * 2 + 1];
            uint32_t q[4] = { u.x, u.y, u.z, u.w };
            INS4A(q, v.x); INS4A(q, v.y); INS4A(q, v.z); INS4A(q, v.w);

            const int t = t0 + tid;
            kstar = (int)(q[0] & 511u);
            const float thr = unpk(q[0]) + WIN;
            heavy = (unpk(q[3]) <= thr);            // 4+ in window -> warp full scan

            if (!heavy && unpk(q[1]) <= thr) {
                // <=3 candidates in window: exact rescore, ascending k, strict <
                const float* xp = x + (size_t)b * DT + t;
                float xn = 0.f;
                #pragma unroll
                for (int d = 0; d < Dc; d++) {
                    const float vv = xp[(size_t)d * Tc];
                    xn = __fadd_rn(xn, __fmul_rn(vv, vv));
                }
                int nc = 2, ck[4];
                ck[0] = (int)(q[0] & 511u); ck[1] = (int)(q[1] & 511u);
                if (unpk(q[2]) <= thr) ck[nc++] = (int)(q[2] & 511u);
                #pragma unroll
                for (int i = 0; i < 2; i++)
                    #pragma unroll
                    for (int j = 0; j < 2; j++)
                        if (j + 1 < nc && ck[j + 1] < ck[j]) {
                            int tk = ck[j]; ck[j] = ck[j + 1]; ck[j + 1] = tk;
                        }
                float be = 3.4e38f;
                for (int i = 0; i < nc; i++) {
                    const int k = ck[i];
                    const float* cr = cb + k * Dc;
                    float dot = 0.f;
                    #pragma unroll
                    for (int d = 0; d < Dc; d++)
                        dot = fmaf(xp[(size_t)d * Tc], __ldg(cr + d), dot);
                    const float s = __fadd_rn(fmaf(-2.f, dot, xn), scn[k]);
                    if (s < be) { be = s; kstar = k; }
                }
            }
        }

        // ---- rare heavy tokens: warp-cooperative exact full scan ----
        if (wid < 4) {
            unsigned hm = __ballot_sync(0xffffffffu, heavy);
            while (hm) {
                const int src = __ffs(hm) - 1; hm &= hm - 1;
                const int t = t0 + wid * 32 + src;
                const float* xp = x + (size_t)b * DT + t;
                float xn = 0.f;
                for (int d = 0; d < Dc; d++) {
                    const float vv = xp[(size_t)d * Tc];
                    xn = __fadd_rn(xn, __fmul_rn(vv, vv));
                }
                float bs = 3.4e38f; int bk = 0;
                for (int j = 0; j < 16; j++) {      // lane covers k = lane*16 .. +15
                    const int k = lane * 16 + j;
                    const float* cr = cb + k * Dc;
                    float dot = 0.f;
                    #pragma unroll
                    for (int d = 0; d < Dc; d++)
                        dot = fmaf(xp[(size_t)d * Tc], __ldg(cr + d), dot);
                    const float s = __fadd_rn(fmaf(-2.f, dot, xn), scn[k]);
                    if (s < bs) { bs = s; bk = k; }
                }
                // warp-reduce: min score, tie -> smaller k (== global first-min)
                #pragma unroll
                for (int off = 16; off; off >>= 1) {
                    const float os = __shfl_xor_sync(0xffffffffu, bs, off);
                    const int   ok = __shfl_xor_sync(0xffffffffu, bk, off);
                    if (os < bs || (os == bs && ok < bk)) { bs = os; bk = ok; }
                }
                if (lane == src) kstar = bk;
            }
        }
        if (tid < 128) skst[tid] = kstar;
        __syncthreads();

        // ---- writeback: 4 groups of 128 (token, output-copy, d-half) ----
        {
            const int tt = tid & 127;
            const int grp = tid >> 7;
            const int half = grp >> 1;
            const int gh = grp & 1;
            if (half == 0 || write_second) {
                const int kst = skst[tt];
                const float4* q4 = (const float4*)(cb + kst * Dc) + gh * 8;
                float* o = out + (size_t)b * DT + (t0 + tt)
                         + (size_t)half * ((size_t)Bc * DT);
                #pragma unroll
                for (int g = 0; g < 8; g++) {
                    const float4 vv = __ldg(q4 + g);
                    const size_t r = (size_t)(4 * (gh * 8 + g)) * Tc;
                    o[r] = vv.x; o[r + Tc] = vv.y; o[r + 2 * Tc] = vv.z; o[r + 3 * Tc] = vv.w;
                }
            }
        }
        __syncthreads();   // skst reuse next tile (A/cand protected by later syncs)
    }
}

extern "C" void kernel_launch(void* const* d_in, const int* in_sizes, int n_in,
                              void* d_out, int out_size)
{
    const float* x  = (const float*)d_in[0];   // [16, 64, 8192] fp32
    const float* cb = (const float*)d_in[1];   // [512, 64] fp32
    float* out = (float*)d_out;                // 2 x [16,64,8192]

    static int inited = 0;
    if (!inited) {
        cudaFuncSetAttribute(vq_main, cudaFuncAttributeMaxDynamicSharedMemorySize,
                             SMEM_TOTAL);
        inited = 1;
    }
    const int write_second = (out_size >= 2 * Bc * DT) ? 1 : 0;

    vq_prep<<<4, 128>>>(cb);
    vq_main<<<GRID, THREADS, SMEM_TOTAL>>>(x, cb, out, write_second);
}

// round 17
// speedup vs baseline: 1.6893x; 1.6893x over previous
#include <cuda_runtime.h>
#include <cuda_bf16.h>
#include <cstdint>

// ---------------- problem constants ----------------
#define Bc 16
#define Dc 64
#define Tc 8192
#define Kc 512
#define DT (Dc * Tc)        // 524288
#define BT (Bc * Tc)        // 131072
#define THREADS 512
#define GRID 148
#define NTILES (BT / 128)   // 1024 token tiles
#define CHUNK_B 16384       // 128 codewords x 64 K bf16 (ch only)
#define WIN 3e-4f           // > deterministic max score err 1.9e-4 + grain 2.2e-5 + pack 2e-6

// ---------------- smem layout ----------------
#define SM_CN   0                            // 512 f32 norms
#define SM_CAND 2048                         // uint4 cand[128][2]
#define SM_KST  6144                         // int kst[128]
#define SM_A    6656                         // 128 tok x 128 k bf16 [xh|xl], 16x16 tiles
#define SM_B    (SM_A + 32768)               // 39424: ALL 4 chunks static, 64KB
#define SMEM_TOTAL (SM_B + 4 * CHUNK_B)      // 104960 B (~102.5 KB)

__device__ __align__(16) unsigned char g_B[4 * CHUNK_B];
__device__ float g_cn[Kc];

// ---------------- helpers ----------------
__device__ __forceinline__ uint32_t smem_u32(const void* p) {
    uint32_t a;
    asm("{ .reg .u64 t; cvta.to.shared.u64 t, %1; cvt.u32.u64 %0, t; }"
        : "=r"(a) : "l"(p));
    return a;
}

#define LDSM4(r0, r1, r2, r3, addr)                                          \
    asm volatile("ldmatrix.sync.aligned.m8n8.x4.shared.b16 {%0,%1,%2,%3}, [%4];" \
        : "=r"(r0), "=r"(r1), "=r"(r2), "=r"(r3) : "r"(addr))

#define MMA_BF16(c, a0, a1, a2, a3, b0, b1)                                  \
    asm volatile("mma.sync.aligned.m16n8k16.row.col.f32.bf16.bf16.f32 "      \
        "{%0,%1,%2,%3}, {%4,%5,%6,%7}, {%8,%9}, {%0,%1,%2,%3};"              \
        : "+f"((c)[0]), "+f"((c)[1]), "+f"((c)[2]), "+f"((c)[3])             \
        : "r"(a0), "r"(a1), "r"(a2), "r"(a3), "r"(b0), "r"(b1))

// packed score|idx: monotone-flipped float in high 23 bits, k in low 9 bits.
__device__ __forceinline__ uint32_t packsk(float s, int k) {
    uint32_t u = __float_as_uint(s);
    u = (u & 0x80000000u) ? ~u : (u | 0x80000000u);
    return (u & 0xFFFFFE00u) | (uint32_t)k;
}
__device__ __forceinline__ float unpk(uint32_t m) {
    m &= 0xFFFFFE00u;
    uint32_t u = (m & 0x80000000u) ? (m & 0x7FFFFFFFu) : ~m;
    return __uint_as_float(u);
}

#define INS4A(q, vv) do { uint32_t _v = (vv);                                \
    if (_v < (q)[3]) {                                                       \
        if (_v < (q)[0])      { (q)[3]=(q)[2]; (q)[2]=(q)[1]; (q)[1]=(q)[0]; (q)[0]=_v; } \
        else if (_v < (q)[1]) { (q)[3]=(q)[2]; (q)[2]=(q)[1]; (q)[1]=_v; }   \
        else if (_v < (q)[2]) { (q)[3]=(q)[2]; (q)[2]=_v; }                  \
        else                  { (q)[3]=_v; } } } while (0)
#define MRG4A(q, st) do {                                                    \
    uint32_t _a=__shfl_xor_sync(0xffffffffu, (q)[0], st);                    \
    uint32_t _b=__shfl_xor_sync(0xffffffffu, (q)[1], st);                    \
    uint32_t _c=__shfl_xor_sync(0xffffffffu, (q)[2], st);                    \
    uint32_t _d=__shfl_xor_sync(0xffffffffu, (q)[3], st);                    \
    INS4A(q,_a); INS4A(q,_b); INS4A(q,_c); INS4A(q,_d); } while (0)

__device__ __forceinline__ uint32_t pack_bf16(__nv_bfloat16 a, __nv_bfloat16 b) {
    uint16_t ua = *(uint16_t*)&a, ub = *(uint16_t*)&b;
    return (uint32_t)ua | ((uint32_t)ub << 16);
}

// ---------------- prep: bake B (ch only) + cn ----------------
__global__ void vq_prep(const float* __restrict__ cb)
{
    int r = blockIdx.x * blockDim.x + threadIdx.x;
    if (r >= Kc) return;
    const float* row = cb + r * Dc;
    unsigned char* base = g_B + (size_t)(r >> 7) * CHUNK_B;
    const int n8 = (r & 127) >> 3, nr = r & 7;
    float cn = 0.f;
    for (int d = 0; d < Dc; d++) {
        float v = row[d];
        cn = __fadd_rn(cn, __fmul_rn(v, v));     // serial ascending (matches ref)
        uint32_t off = (uint32_t)(((d >> 4) * 16 + n8) * 256 + nr * 32 + (d & 15) * 2);
        *(__nv_bfloat16*)(base + off) = __float2bfloat16_rn(v);
    }
    g_cn[r] = cn;
}

// ---------------- per-chunk compute: B frags in regs; h-pass then l-pass ----
// same-acc MMA dependency distance = 8 (was 2) -> HMMA latency hidden
__device__ __forceinline__ void do_chunk(uint32_t sB, int kq,
                                         const uint32_t (&afr)[8][4],
                                         const float* scn,
                                         uint32_t (&qA)[4], uint32_t (&qB)[4])
{
    float acc[8][4];
    #pragma unroll
    for (int a = 0; a < 8; a++)
        #pragma unroll
        for (int j = 0; j < 4; j++) acc[a][j] = 0.f;

    #pragma unroll
    for (int ktb = 0; ktb < 4; ktb++) {
        uint32_t r[4][4];
        #pragma unroll
        for (int pr = 0; pr < 4; pr++)
            LDSM4(r[pr][0], r[pr][1], r[pr][2], r[pr][3],
                  sB + (uint32_t)(ktb * 16 + pr * 2) * 256);
        // h pass: 8 independent MMAs
        #pragma unroll
        for (int pr = 0; pr < 4; pr++) {
            MMA_BF16(acc[2 * pr],     afr[ktb][0], afr[ktb][1], afr[ktb][2], afr[ktb][3], r[pr][0], r[pr][1]);
            MMA_BF16(acc[2 * pr + 1], afr[ktb][0], afr[ktb][1], afr[ktb][2], afr[ktb][3], r[pr][2], r[pr][3]);
        }
        // l pass: same accs, 8 MMAs later -> no exposed latency
        #pragma unroll
        for (int pr = 0; pr < 4; pr++) {
            MMA_BF16(acc[2 * pr],     afr[ktb + 4][0], afr[ktb + 4][1], afr[ktb + 4][2], afr[ktb + 4][3], r[pr][0], r[pr][1]);
            MMA_BF16(acc[2 * pr + 1], afr[ktb + 4][0], afr[ktb + 4][1], afr[ktb + 4][2], afr[ktb + 4][3], r[pr][2], r[pr][3]);
        }
    }
    #pragma unroll
    for (int a = 0; a < 8; a++) {
        const int k = kq + a * 8;
        const float2 cn2 = *(const float2*)(scn + k);
        INS4A(qA, packsk(fmaf(-2.f, acc[a][0], cn2.x), k));
        INS4A(qA, packsk(fmaf(-2.f, acc[a][1], cn2.y), k + 1));
        INS4A(qB, packsk(fmaf(-2.f, acc[a][2], cn2.x), k));
        INS4A(qB, packsk(fmaf(-2.f, acc[a][3], cn2.y), k + 1));
    }
}

// ---------------- main ----------------
__global__ __launch_bounds__(THREADS, 1)
void vq_main(const float* __restrict__ x,
             const float* __restrict__ cb,
             float* __restrict__ out,
             int write_second)
{
    extern __shared__ char smem[];
    const uint32_t sb = smem_u32(smem);
    const int tid = threadIdx.x, wid = tid >> 5, lane = tid & 31;
    const int mt = wid >> 1, nh = wid & 1;     // M-tile 0..7, N-half 0..1
    float* scn = (float*)(smem + SM_CN);
    uint4* cand = (uint4*)(smem + SM_CAND);
    int* skst = (int*)(smem + SM_KST);

    for (int i = tid; i < Kc; i += THREADS) scn[i] = g_cn[i];

    // entire baked codebook (64KB) -> smem ONCE
    #pragma unroll
    for (int i = 0; i < 8; i++) {
        uint32_t s = sb + SM_B + (uint32_t)(tid + i * THREADS) * 16;
        const unsigned char* g = g_B + (size_t)(tid + i * THREADS) * 16;
        asm volatile("cp.async.cg.shared.global [%0], [%1], 16;" :: "r"(s), "l"(g));
    }
    asm volatile("cp.async.commit_group;" ::: "memory");

    const uint32_t aOff = (uint32_t)(lane & 15) * 32 + (uint32_t)(lane >> 4) * 16;
    const uint32_t bOff = (uint32_t)(lane & 7) * 32 + (uint32_t)((lane >> 3) & 1) * 16
                        + (uint32_t)(lane >> 4) * 256 + (uint32_t)nh * 2048;
    const uint32_t sA = sb + SM_A;

    for (int tile = blockIdx.x; tile < NTILES; tile += GRID) {
        const int b = tile >> 6, t0 = (tile & 63) * 128;
        const float* xbase = x + (size_t)b * DT + t0;

        // ---- A build: [xh | xl] 128x128, STS.128 (2 iters/thread) ----
        #pragma unroll
        for (int j = 0; j < 2; j++) {
            const int i = tid + j * THREADS;
            const int tl = i & 127, o = i >> 7;        // d-octet 0..7
            float v[8];
            #pragma unroll
            for (int e = 0; e < 8; e++) v[e] = xbase[(size_t)(o * 8 + e) * Tc + tl];
            uint4 hp, lp;
            {
                uint32_t h[4], l[4];
                #pragma unroll
                for (int p = 0; p < 4; p++) {
                    __nv_bfloat16 h0 = __float2bfloat16_rn(v[2 * p]);
                    __nv_bfloat16 h1 = __float2bfloat16_rn(v[2 * p + 1]);
                    __nv_bfloat16 l0 = __float2bfloat16_rn(v[2 * p]     - __bfloat162float(h0));
                    __nv_bfloat16 l1 = __float2bfloat16_rn(v[2 * p + 1] - __bfloat162float(h1));
                    h[p] = pack_bf16(h0, h1);
                    l[p] = pack_bf16(l0, l1);
                }
                hp = make_uint4(h[0], h[1], h[2], h[3]);
                lp = make_uint4(l[0], l[1], l[2], l[3]);
            }
            const uint32_t base = (uint32_t)((tl >> 4) * 8 + (o >> 1)) * 512
                                + (uint32_t)(tl & 15) * 32 + (uint32_t)(o & 1) * 16;
            *(uint4*)(smem + SM_A + base)            = hp;   // xh at kt = o>>1
            *(uint4*)(smem + SM_A + base + 4 * 512)  = lp;   // xl at kt = 4 + (o>>1)
        }
        asm volatile("cp.async.wait_group 0;" ::: "memory");   // first tile: B arrival
        __syncthreads();

        // ---- A fragments once per tile ----
        uint32_t afr[8][4];
        #pragma unroll
        for (int kt = 0; kt < 8; kt++)
            LDSM4(afr[kt][0], afr[kt][1], afr[kt][2], afr[kt][3],
                  sA + (uint32_t)(mt * 8 + kt) * 512 + aOff);

        uint32_t qA[4] = {0xFFFFFFFFu, 0xFFFFFFFFu, 0xFFFFFFFFu, 0xFFFFFFFFu};
        uint32_t qB[4] = {0xFFFFFFFFu, 0xFFFFFFFFu, 0xFFFFFFFFu, 0xFFFFFFFFu};
        const int kqL = nh * 64 + 2 * (lane & 3);

        // ---- 4 chunks, ALL static in smem: no barriers, warps skew freely ----
        #pragma unroll 1
        for (int c = 0; c < 4; c++)
            do_chunk(sb + SM_B + (uint32_t)c * CHUNK_B + bOff,
                     c * 128 + kqL, afr, scn, qA, qB);

        // ---- quad merge -> per-row-half top4 ----
        MRG4A(qA, 1); MRG4A(qA, 2);
        MRG4A(qB, 1); MRG4A(qB, 2);
        if ((lane & 3) == 0) {
            const int rA = mt * 16 + (lane >> 2);
            cand[rA * 2 + nh]       = make_uint4(qA[0], qA[1], qA[2], qA[3]);
            cand[(rA + 8) * 2 + nh] = make_uint4(qB[0], qB[1], qB[2], qB[3]);
        }
        __syncthreads();

        // ---- finalize (threads 0..127): window check + exact rescore ----
        int kstar = 0;
        bool heavy = false;
        if (tid < 128) {
            const uint4 u = cand[tid * 2], v = cand[tid * 2 + 1];
            uint32_t q[4] = { u.x, u.y, u.z, u.w };
            INS4A(q, v.x); INS4A(q, v.y); INS4A(q, v.z); INS4A(q, v.w);

            const int t = t0 + tid;
            kstar = (int)(q[0] & 511u);
            const float thr = unpk(q[0]) + WIN;
            heavy = (unpk(q[3]) <= thr);            // 4+ in window -> warp full scan

            if (!heavy && unpk(q[1]) <= thr) {
                // <=3 candidates in window: exact rescore, ascending k, strict <
                const float* xp = x + (size_t)b * DT + t;
                float xn = 0.f;
                #pragma unroll
                for (int d = 0; d < Dc; d++) {
                    const float vv = xp[(size_t)d * Tc];
                    xn = __fadd_rn(xn, __fmul_rn(vv, vv));
                }
                int nc = 2, ck[4];
                ck[0] = (int)(q[0] & 511u); ck[1] = (int)(q[1] & 511u);
                if (unpk(q[2]) <= thr) ck[nc++] = (int)(q[2] & 511u);
                #pragma unroll
                for (int i = 0; i < 2; i++)
                    #pragma unroll
                    for (int j = 0; j < 2; j++)
                        if (j + 1 < nc && ck[j + 1] < ck[j]) {
                            int tk = ck[j]; ck[j] = ck[j + 1]; ck[j + 1] = tk;
                        }
                float be = 3.4e38f;
                for (int i = 0; i < nc; i++) {
                    const int k = ck[i];
                    const float* cr = cb + k * Dc;
                    float dot = 0.f;
                    #pragma unroll
                    for (int d = 0; d < Dc; d++)
                        dot = fmaf(xp[(size_t)d * Tc], __ldg(cr + d), dot);
                    const float s = __fadd_rn(fmaf(-2.f, dot, xn), scn[k]);
                    if (s < be) { be = s; kstar = k; }
                }
            }
        }

        // ---- rare heavy tokens (~3e-3/tile): warp-cooperative exact full scan ----
        if (wid < 4) {
            unsigned hm = __ballot_sync(0xffffffffu, heavy);
            while (hm) {
                const int src = __ffs(hm) - 1; hm &= hm - 1;
                const int t = t0 + wid * 32 + src;
                const float* xp = x + (size_t)b * DT + t;
                float xn = 0.f;
                for (int d = 0; d < Dc; d++) {
                    const float vv = xp[(size_t)d * Tc];
                    xn = __fadd_rn(xn, __fmul_rn(vv, vv));
                }
                float bs = 3.4e38f; int bk = 0;
                for (int j = 0; j < 16; j++) {      // lane covers k = lane*16 .. +15
                    const int k = lane * 16 + j;
                    const float* cr = cb + k * Dc;
                    float dot = 0.f;
                    #pragma unroll
                    for (int d = 0; d < Dc; d++)
                        dot = fmaf(xp[(size_t)d * Tc], __ldg(cr + d), dot);
                    const float s = __fadd_rn(fmaf(-2.f, dot, xn), scn[k]);
                    if (s < bs) { bs = s; bk = k; }
                }
                // warp-reduce: min score, tie -> smaller k (== global first-min)
                #pragma unroll
                for (int off = 16; off; off >>= 1) {
                    const float os = __shfl_xor_sync(0xffffffffu, bs, off);
                    const int   ok = __shfl_xor_sync(0xffffffffu, bk, off);
                    if (os < bs || (os == bs && ok < bk)) { bs = os; bk = ok; }
                }
                if (lane == src) kstar = bk;
            }
        }
        if (tid < 128) skst[tid] = kstar;
        __syncthreads();

        // ---- writeback: 4 groups of 128 (token, output-copy, d-half) ----
        {
            const int tt = tid & 127;
            const int grp = tid >> 7;
            const int half = grp >> 1;
            const int gh = grp & 1;
            if (half == 0 || write_second) {
                const int kst = skst[tt];
                const float4* q4 = (const float4*)(cb + kst * Dc) + gh * 8;
                float* o = out + (size_t)b * DT + (t0 + tt)
                         + (size_t)half * ((size_t)Bc * DT);
                #pragma unroll
                for (int g = 0; g < 8; g++) {
                    const float4 vv = __ldg(q4 + g);
                    const size_t r = (size_t)(4 * (gh * 8 + g)) * Tc;
                    o[r] = vv.x; o[r + Tc] = vv.y; o[r + 2 * Tc] = vv.z; o[r + 3 * Tc] = vv.w;
                }
            }
        }
        __syncthreads();   // skst reuse next tile (A/cand protected by later syncs)
    }
}

extern "C" void kernel_launch(void* const* d_in, const int* in_sizes, int n_in,
                              void* d_out, int out_size)
{
    const float* x  = (const float*)d_in[0];   // [16, 64, 8192] fp32
    const float* cb = (const float*)d_in[1];   // [512, 64] fp32
    float* out = (float*)d_out;                // 2 x [16,64,8192]

    static int inited = 0;
    if (!inited) {
        cudaFuncSetAttribute(vq_main, cudaFuncAttributeMaxDynamicSharedMemorySize,
                             SMEM_TOTAL);
        inited = 1;
    }
    const int write_second = (out_size >= 2 * Bc * DT) ? 1 : 0;

    vq_prep<<<4, 128>>>(cb);
    vq_main<<<GRID, THREADS, SMEM_TOTAL>>>(x, cb, out, write_second);
}